// round 5
// baseline (speedup 1.0000x reference)
#include <cuda_runtime.h>

#define HIDN 128
#define MAXN 100001
#define MAXE 1600000
#define MAXK 256
#define RS   132            // sAT row stride (floats), 16B-aligned rows, bank-skewed
#define TILE_ROWS 128
#define GEMM_SMEM ((MAXK*HIDN + TILE_ROWS*RS)*4)

// ---------------- scratch (no allocations allowed) ----------------
__device__ float g_h [100000*HIDN];
__device__ float g_h1[100000*HIDN];
__device__ float g_m [100000*HIDN];   // also feature scratch (needs 10.4M floats < 12.8M)
__device__ int   g_deg[MAXN];
__device__ int   g_off[MAXN];
__device__ int   g_cur[MAXN];
__device__ int   g_csrc[MAXE];
__device__ int   g_bsums[256];

// ---------------- f32x2 helpers ----------------
__device__ __forceinline__ unsigned long long splat2(float x){
    unsigned long long r;
    asm("mov.b64 %0, {%1, %1};" : "=l"(r) : "f"(x));
    return r;
}
__device__ __forceinline__ void ffma2(unsigned long long& d, unsigned long long a, unsigned long long b){
    asm("fma.rn.f32x2 %0, %1, %2, %0;" : "+l"(d) : "l"(a), "l"(b));
}
__device__ __forceinline__ float2 unpk2(unsigned long long v){
    float2 f;
    asm("mov.b64 {%0, %1}, %2;" : "=f"(f.x), "=f"(f.y) : "l"(v));
    return f;
}

// ---------------- feature builders ----------------
__global__ void build_pol_feat(const float* __restrict__ x, const int* __restrict__ sidx,
                               const float* __restrict__ semb, float* __restrict__ out, int np){
    int total = np*72;
    for (int i = blockIdx.x*blockDim.x + threadIdx.x; i < total; i += gridDim.x*blockDim.x){
        int row = i/72, k = i - row*72;
        out[i] = (k < 64) ? x[row*64 + k] : semb[sidx[row]*8 + (k-64)];
    }
}
__global__ void build_comp_feat(const float* __restrict__ x, const int* __restrict__ sct,
                                const int* __restrict__ ind, const float* __restrict__ semb,
                                const float* __restrict__ iemb, float* __restrict__ out, int nc){
    int total = nc*112;
    for (int i = blockIdx.x*blockDim.x + threadIdx.x; i < total; i += gridDim.x*blockDim.x){
        int row = i/112, k = i - row*112;
        float v;
        if (k < 96)       v = x[row*96 + k];
        else if (k < 104) v = semb[sct[row]*8 + (k-96)];
        else              v = iemb[ind[row]*8 + (k-104)];
        out[i] = v;
    }
}

// ---------------- CSR build ----------------
__global__ void zero_deg(int n){
    int i = blockIdx.x*blockDim.x + threadIdx.x;
    if (i < n) g_deg[i] = 0;
}
__global__ void count_deg(const int* __restrict__ dstv, int E){
    for (int e = blockIdx.x*blockDim.x + threadIdx.x; e < E; e += gridDim.x*blockDim.x)
        atomicAdd(&g_deg[dstv[e]], 1);
}
__global__ void scan_blocks(int n){
    __shared__ int s[1024];
    int t = threadIdx.x;
    int g = blockIdx.x*1024 + t;
    int v = (g < n) ? g_deg[g] : 0;
    s[t] = v; __syncthreads();
    #pragma unroll
    for (int d = 1; d < 1024; d <<= 1){
        int x = (t >= d) ? s[t-d] : 0;
        __syncthreads();
        s[t] += x;
        __syncthreads();
    }
    if (g < n) g_off[g] = s[t] - v;           // block-local exclusive
    if (t == 1023) g_bsums[blockIdx.x] = s[1023];
}
__global__ void scan_bsums(int nb, int n, int total){
    __shared__ int s[256];
    int t = threadIdx.x;
    int v = (t < nb) ? g_bsums[t] : 0;
    s[t] = v; __syncthreads();
    #pragma unroll
    for (int d = 1; d < 256; d <<= 1){
        int x = (t >= d) ? s[t-d] : 0;
        __syncthreads();
        s[t] += x;
        __syncthreads();
    }
    if (t < nb) g_bsums[t] = s[t] - v;
    if (t == 0) g_off[n] = total;
}
__global__ void add_bsums(int n){
    int g = blockIdx.x*1024 + threadIdx.x;
    if (g < n){
        int o = g_off[g] + g_bsums[blockIdx.x];
        g_off[g] = o;
        g_cur[g] = o;
    }
}
__global__ void fill_csr(const int* __restrict__ srcv, const int* __restrict__ dstv, int E){
    for (int e = blockIdx.x*blockDim.x + threadIdx.x; e < E; e += gridDim.x*blockDim.x){
        int d = dstv[e];
        int p = atomicAdd(&g_cur[d], 1);
        g_csrc[p] = srcv[e];
    }
}

// ---------------- mean aggregation: one warp per dst node ----------------
__global__ void agg_mean(const float* __restrict__ hin, float* __restrict__ mout, int n){
    int w    = (blockIdx.x*blockDim.x + threadIdx.x) >> 5;
    int lane = threadIdx.x & 31;
    if (w >= n) return;
    int beg = g_off[w], end = g_off[w+1];
    const float* base = hin + lane*4;
    float4 acc = make_float4(0.f, 0.f, 0.f, 0.f);
    int j = beg;
    for (; j + 8 <= end; j += 8){
        float4 v[8];
        #pragma unroll
        for (int t = 0; t < 8; t++){
            int s = g_csrc[j+t];
            v[t] = *(const float4*)(base + (size_t)s*HIDN);
        }
        #pragma unroll
        for (int t = 0; t < 8; t++){
            acc.x += v[t].x; acc.y += v[t].y; acc.z += v[t].z; acc.w += v[t].w;
        }
    }
    for (; j < end; ++j){
        int s = g_csrc[j];
        float4 v = *(const float4*)(base + (size_t)s*HIDN);
        acc.x += v.x; acc.y += v.y; acc.z += v.z; acc.w += v.w;
    }
    int d = end - beg;
    float inv = 1.0f / (float)(d > 0 ? d : 1);
    float4 r = make_float4(acc.x*inv, acc.y*inv, acc.z*inv, acc.w*inv);
    *(float4*)(mout + (size_t)w*HIDN + lane*4) = r;
}

// ---------------- fused GEMM: C = act(A1@W1 + A2@W2 + b), N=128 ----------------
// Persistent blocks. W (K1+K2 x 128) staged once in smem; A tile staged transposed.
// 8x8 register tile per thread (rows split rg*4..+3 and 64+rg*4..+3, cols likewise)
// so all inner-loop LDS are conflict-free float4 / b64 reads. f32x2 FMA -> 2 MAC/instr.
__global__ void __launch_bounds__(256, 1)
gemm128(const float* __restrict__ A1, int K1,
        const float* __restrict__ A2, int K2,
        const float* __restrict__ W1, const float* __restrict__ W2,
        const float* __restrict__ bias, float* __restrict__ C,
        int nrows, int relu)
{
    extern __shared__ float sm[];
    float* sW  = sm;                // [Kt][128]
    float* sAT = sm + MAXK*HIDN;    // [k up to 128][RS]
    int tid = threadIdx.x;
    int Kt = K1 + K2;

    // stage W (from two sources)
    for (int idx = tid; idx < Kt*HIDN; idx += 256){
        int k = idx >> 7, c = idx & 127;
        sW[idx] = (k < K1) ? W1[k*HIDN + c] : W2[(k-K1)*HIDN + c];
    }
    int cg = tid >> 4;          // 0..15 -> col groups
    int rg = tid & 15;          // 0..15 -> row groups
    int c_lo = cg*4, c_hi = 64 + cg*4;
    float b[8];
    #pragma unroll
    for (int j = 0; j < 4; j++){ b[j] = bias[c_lo+j]; b[4+j] = bias[c_hi+j]; }
    __syncthreads();

    int ntiles = (nrows + TILE_ROWS - 1) / TILE_ROWS;
    for (int tile = blockIdx.x; tile < ntiles; tile += gridDim.x){
        int rowbase = tile * TILE_ROWS;
        unsigned long long acc[8][4];
        #pragma unroll
        for (int i = 0; i < 8; i++)
            #pragma unroll
            for (int q = 0; q < 4; q++) acc[i][q] = 0ull;

        #pragma unroll
        for (int pass = 0; pass < 2; pass++){
            const float* A = pass ? A2 : A1;
            int Kc    = pass ? K2 : K1;
            int kofsW = pass ? K1 : 0;
            if (Kc == 0) continue;

            __syncthreads();
            // stage A tile transposed: sAT[k][row]
            for (int idx = tid; idx < Kc*TILE_ROWS; idx += 256){
                int row = idx / Kc;
                int k   = idx - row*Kc;
                int r = rowbase + row;
                float v = (r < nrows) ? A[(size_t)r*Kc + k] : 0.f;
                sAT[k*RS + row] = v;
            }
            __syncthreads();

            #pragma unroll 2
            for (int k = 0; k < Kc; ++k){
                const float* atk = &sAT[k*RS];
                float4 alo = *(const float4*)(atk + rg*4);
                float4 ahi = *(const float4*)(atk + 64 + rg*4);
                const unsigned long long* wrow =
                    (const unsigned long long*)(sW + ((kofsW + k) << 7));
                unsigned long long w0 = wrow[cg*2];
                unsigned long long w1 = wrow[cg*2 + 1];
                unsigned long long w2 = wrow[32 + cg*2];
                unsigned long long w3 = wrow[32 + cg*2 + 1];
                float av[8] = {alo.x, alo.y, alo.z, alo.w, ahi.x, ahi.y, ahi.z, ahi.w};
                #pragma unroll
                for (int i = 0; i < 8; i++){
                    unsigned long long a2 = splat2(av[i]);
                    ffma2(acc[i][0], a2, w0);
                    ffma2(acc[i][1], a2, w1);
                    ffma2(acc[i][2], a2, w2);
                    ffma2(acc[i][3], a2, w3);
                }
            }
        }

        // epilogue: bias (+relu), store two float4 per row
        #pragma unroll
        for (int i = 0; i < 8; i++){
            int lrow = (i < 4) ? (rg*4 + i) : (64 + rg*4 + (i-4));
            int r = rowbase + lrow;
            if (r < nrows){
                float2 p0 = unpk2(acc[i][0]), p1 = unpk2(acc[i][1]);
                float2 p2 = unpk2(acc[i][2]), p3 = unpk2(acc[i][3]);
                float o0 = p0.x + b[0], o1 = p0.y + b[1], o2 = p1.x + b[2], o3 = p1.y + b[3];
                float o4 = p2.x + b[4], o5 = p2.y + b[5], o6 = p3.x + b[6], o7 = p3.y + b[7];
                if (relu){
                    o0 = fmaxf(o0,0.f); o1 = fmaxf(o1,0.f); o2 = fmaxf(o2,0.f); o3 = fmaxf(o3,0.f);
                    o4 = fmaxf(o4,0.f); o5 = fmaxf(o5,0.f); o6 = fmaxf(o6,0.f); o7 = fmaxf(o7,0.f);
                }
                *(float4*)(C + (size_t)r*HIDN + c_lo) = make_float4(o0,o1,o2,o3);
                *(float4*)(C + (size_t)r*HIDN + c_hi) = make_float4(o4,o5,o6,o7);
            }
        }
    }
}

// ---------------- launch ----------------
extern "C" void kernel_launch(void* const* d_in, const int* in_sizes, int n_in,
                              void* d_out, int out_size){
    const float* x_pol  = (const float*)d_in[0];
    const int*   psidx  = (const int*)  d_in[1];
    const float* x_comp = (const float*)d_in[2];
    const int*   csct   = (const int*)  d_in[3];
    const int*   cind   = (const int*)  d_in[4];
    const int*   eidx   = (const int*)  d_in[5];
    const float* semb   = (const float*)d_in[6];
    const float* scemb  = (const float*)d_in[7];
    const float* iemb   = (const float*)d_in[8];
    const float* W_pol  = (const float*)d_in[9];
    const float* b_pol  = (const float*)d_in[10];
    const float* W_comp = (const float*)d_in[11];
    const float* b_comp = (const float*)d_in[12];
    const float* Wl1    = (const float*)d_in[13];
    const float* bl1    = (const float*)d_in[14];
    const float* Wr1    = (const float*)d_in[15];
    const float* Wl2    = (const float*)d_in[16];
    const float* bl2    = (const float*)d_in[17];
    const float* Wr2    = (const float*)d_in[18];
    float* out = (float*)d_out;

    int NP = in_sizes[0]/64;
    int NC = in_sizes[2]/96;
    int E  = in_sizes[5]/2;
    int N  = NP + NC;
    const int* srcv = eidx;
    const int* dstv = eidx + E;

    float *hP, *h1P, *mP;
    cudaGetSymbolAddress((void**)&hP,  g_h);
    cudaGetSymbolAddress((void**)&h1P, g_h1);
    cudaGetSymbolAddress((void**)&mP,  g_m);

    cudaFuncSetAttribute(gemm128, cudaFuncAttributeMaxDynamicSharedMemorySize, GEMM_SMEM);

    float* featP = mP;
    float* featC = mP + (size_t)NP*72;

    // encoders
    build_pol_feat <<<1024, 256>>>(x_pol, psidx, semb, featP, NP);
    build_comp_feat<<<2048, 256>>>(x_comp, csct, cind, scemb, iemb, featC, NC);
    gemm128<<<148, 256, GEMM_SMEM>>>(featP, 72,  nullptr, 0, W_pol,  nullptr, b_pol,
                                     hP, NP, 1);
    gemm128<<<148, 256, GEMM_SMEM>>>(featC, 112, nullptr, 0, W_comp, nullptr, b_comp,
                                     hP + (size_t)NP*HIDN, NC, 1);

    // CSR build (shared by both layers)
    int NB = (N + 1023) / 1024;
    zero_deg   <<<NB, 1024>>>(N);
    count_deg  <<<2048, 256>>>(dstv, E);
    scan_blocks<<<NB, 1024>>>(N);
    scan_bsums <<<1, 256>>>(NB, N, E);
    add_bsums  <<<NB, 1024>>>(N);
    fill_csr   <<<2048, 256>>>(srcv, dstv, E);

    // SAGE layer 1
    agg_mean<<<(N + 7)/8, 256>>>(hP, mP, N);
    gemm128 <<<148, 256, GEMM_SMEM>>>(mP, HIDN, hP, HIDN, Wl1, Wr1, bl1, h1P, N, 1);

    // SAGE layer 2 -> d_out
    agg_mean<<<(N + 7)/8, 256>>>(h1P, mP, N);
    gemm128 <<<148, 256, GEMM_SMEM>>>(mP, HIDN, h1P, HIDN, Wl2, Wr2, bl2, out, N, 0);
}

// round 9
// speedup vs baseline: 1.7606x; 1.7606x over previous
#include <cuda_runtime.h>

#define HIDN 128
#define MAXN 100001
#define MAXE 1600000
#define RS   132            // sAT row stride (floats); 16B-aligned rows
#define TILE_ROWS 128

// ---------------- scratch (no allocations allowed) ----------------
__device__ float g_h [100000*HIDN];
__device__ float g_h1[100000*HIDN];
__device__ float g_m [100000*HIDN];
__device__ int   g_deg[MAXN];
__device__ int   g_off[MAXN];
__device__ int   g_cur[MAXN];
__device__ int   g_csrc[MAXE];
__device__ int   g_bsums[256];

// ---------------- f32x2 helpers ----------------
__device__ __forceinline__ unsigned long long splat2(float x){
    unsigned long long r;
    asm("mov.b64 %0, {%1, %1};" : "=l"(r) : "f"(x));
    return r;
}
__device__ __forceinline__ void ffma2(unsigned long long& d, unsigned long long a, unsigned long long b){
    asm("fma.rn.f32x2 %0, %1, %2, %0;" : "+l"(d) : "l"(a), "l"(b));
}
__device__ __forceinline__ float2 unpk2(unsigned long long v){
    float2 f;
    asm("mov.b64 {%0, %1}, %2;" : "=f"(f.x), "=f"(f.y) : "l"(v));
    return f;
}

// ---------------- CSR build ----------------
__global__ void zero_deg(int n){
    int i = blockIdx.x*blockDim.x + threadIdx.x;
    if (i < n) g_deg[i] = 0;
}
__global__ void count_deg(const int* __restrict__ dstv, int E){
    for (int e = blockIdx.x*blockDim.x + threadIdx.x; e < E; e += gridDim.x*blockDim.x)
        atomicAdd(&g_deg[dstv[e]], 1);
}
__global__ void scan_blocks(int n){
    __shared__ int s[1024];
    int t = threadIdx.x;
    int g = blockIdx.x*1024 + t;
    int v = (g < n) ? g_deg[g] : 0;
    s[t] = v; __syncthreads();
    #pragma unroll
    for (int d = 1; d < 1024; d <<= 1){
        int x = (t >= d) ? s[t-d] : 0;
        __syncthreads();
        s[t] += x;
        __syncthreads();
    }
    if (g < n) g_off[g] = s[t] - v;
    if (t == 1023) g_bsums[blockIdx.x] = s[1023];
}
__global__ void scan_bsums(int nb, int n, int total){
    __shared__ int s[256];
    int t = threadIdx.x;
    int v = (t < nb) ? g_bsums[t] : 0;
    s[t] = v; __syncthreads();
    #pragma unroll
    for (int d = 1; d < 256; d <<= 1){
        int x = (t >= d) ? s[t-d] : 0;
        __syncthreads();
        s[t] += x;
        __syncthreads();
    }
    if (t < nb) g_bsums[t] = s[t] - v;
    if (t == 0) g_off[n] = total;
}
__global__ void add_bsums(int n){
    int g = blockIdx.x*1024 + threadIdx.x;
    if (g < n){
        int o = g_off[g] + g_bsums[blockIdx.x];
        g_off[g] = o;
        g_cur[g] = o;
    }
}
__global__ void fill_csr(const int* __restrict__ srcv, const int* __restrict__ dstv, int E){
    for (int e = blockIdx.x*blockDim.x + threadIdx.x; e < E; e += gridDim.x*blockDim.x){
        int d = dstv[e];
        int p = atomicAdd(&g_cur[d], 1);
        g_csrc[p] = srcv[e];
    }
}

// ---------------- mean aggregation: one warp per dst node ----------------
__global__ void agg_mean(const float* __restrict__ hin, float* __restrict__ mout, int n){
    int w    = (blockIdx.x*blockDim.x + threadIdx.x) >> 5;
    int lane = threadIdx.x & 31;
    if (w >= n) return;
    int beg = g_off[w], end = g_off[w+1];
    const float* base = hin + lane*4;
    float4 acc = make_float4(0.f, 0.f, 0.f, 0.f);
    int j = beg;
    for (; j + 16 <= end; j += 16){
        float4 v[16];
        #pragma unroll
        for (int t = 0; t < 16; t++){
            int s = g_csrc[j+t];
            v[t] = *(const float4*)(base + (size_t)s*HIDN);
        }
        #pragma unroll
        for (int t = 0; t < 16; t++){
            acc.x += v[t].x; acc.y += v[t].y; acc.z += v[t].z; acc.w += v[t].w;
        }
    }
    for (; j + 4 <= end; j += 4){
        float4 v[4];
        #pragma unroll
        for (int t = 0; t < 4; t++){
            int s = g_csrc[j+t];
            v[t] = *(const float4*)(base + (size_t)s*HIDN);
        }
        #pragma unroll
        for (int t = 0; t < 4; t++){
            acc.x += v[t].x; acc.y += v[t].y; acc.z += v[t].z; acc.w += v[t].w;
        }
    }
    for (; j < end; ++j){
        int s = g_csrc[j];
        float4 v = *(const float4*)(base + (size_t)s*HIDN);
        acc.x += v.x; acc.y += v.y; acc.z += v.z; acc.w += v.w;
    }
    int d = end - beg;
    float inv = 1.0f / (float)(d > 0 ? d : 1);
    float4 r = make_float4(acc.x*inv, acc.y*inv, acc.z*inv, acc.w*inv);
    *(float4*)(mout + (size_t)w*HIDN + lane*4) = r;
}

// ---------------- fused GEMM: C = act(A1@W1 + A2@W2 + b), N=128 ----------------
// Templated on K1/K2 (compile-time index math) and a loader mode that fuses the
// encoder feature concat (x || emb gathers) directly into A-tile staging.
// Inner loop is software-pipelined: k+1's LDS prefetched into regs during k's FMAs.
enum { MPLAIN = 0, MPOL = 1, MCOMP = 2 };

// Stage one pass's A tile transposed into sAT[k][row].
// Thread item = (rowquad rq, k): 4 coalesced LDG.32 (consecutive k across warp),
// one conflict-free STS.128 of 4 consecutive rows.
template<int Kc, int MODE>
__device__ __forceinline__ void stage_A(
    float* __restrict__ sAT, const float* __restrict__ A,
    const int* __restrict__ i0, const int* __restrict__ i1,
    const float* __restrict__ e0, const float* __restrict__ e1,
    int rowbase, int nrows, int tid)
{
    for (int idx = tid; idx < 32*Kc; idx += 256){
        int rq = idx / Kc;            // compile-time divisor -> mul/shift
        int k  = idx - rq*Kc;
        int r0 = rowbase + rq*4;
        float v[4];
        #pragma unroll
        for (int i = 0; i < 4; i++){
            int r = r0 + i;
            float x = 0.f;
            if (r < nrows){
                if (MODE == MPLAIN){
                    x = A[(size_t)r*Kc + k];
                } else if (MODE == MPOL){
                    x = (k < 64) ? A[(size_t)r*64 + k]
                                 : e0[i0[r]*8 + (k-64)];
                } else { // MCOMP
                    if (k < 96)       x = A[(size_t)r*96 + k];
                    else if (k < 104) x = e0[i0[r]*8 + (k-96)];
                    else              x = e1[i1[r]*8 + (k-104)];
                }
            }
            v[i] = x;
        }
        *(float4*)(sAT + (size_t)k*RS + rq*4) = make_float4(v[0],v[1],v[2],v[3]);
    }
}

template<int Kc>
__device__ __forceinline__ void mma_pass(
    const float* __restrict__ sAT, const float* __restrict__ sW, int kofsW,
    int rg, int cg, unsigned long long acc[8][4])
{
    // prologue: k = 0
    float4 alo = *(const float4*)(sAT + rg*4);
    float4 ahi = *(const float4*)(sAT + 64 + rg*4);
    const unsigned long long* wr0 = (const unsigned long long*)(sW + ((size_t)kofsW << 7));
    unsigned long long w0 = wr0[cg*2], w1 = wr0[cg*2+1];
    unsigned long long w2 = wr0[32+cg*2], w3 = wr0[32+cg*2+1];

    #pragma unroll 4
    for (int k = 0; k < Kc; ++k){
        float4 nalo = alo, nahi = ahi;
        unsigned long long nw0 = w0, nw1 = w1, nw2 = w2, nw3 = w3;
        if (k + 1 < Kc){
            const float* atn = sAT + (size_t)(k+1)*RS;
            nalo = *(const float4*)(atn + rg*4);
            nahi = *(const float4*)(atn + 64 + rg*4);
            const unsigned long long* wn =
                (const unsigned long long*)(sW + ((size_t)(kofsW + k + 1) << 7));
            nw0 = wn[cg*2];      nw1 = wn[cg*2+1];
            nw2 = wn[32+cg*2];   nw3 = wn[32+cg*2+1];
        }
        float av[8] = {alo.x, alo.y, alo.z, alo.w, ahi.x, ahi.y, ahi.z, ahi.w};
        #pragma unroll
        for (int i = 0; i < 8; i++){
            unsigned long long a2 = splat2(av[i]);
            ffma2(acc[i][0], a2, w0);
            ffma2(acc[i][1], a2, w1);
            ffma2(acc[i][2], a2, w2);
            ffma2(acc[i][3], a2, w3);
        }
        alo = nalo; ahi = nahi;
        w0 = nw0; w1 = nw1; w2 = nw2; w3 = nw3;
    }
}

template<int K1, int K2, int MODE>
__global__ void __launch_bounds__(256)
gemm_t(const float* __restrict__ A1, const float* __restrict__ A2,
       const int* __restrict__ i0, const int* __restrict__ i1,
       const float* __restrict__ e0, const float* __restrict__ e1,
       const float* __restrict__ W1, const float* __restrict__ W2,
       const float* __restrict__ bias, float* __restrict__ C,
       int nrows, int relu)
{
    extern __shared__ float sm[];
    constexpr int KT = K1 + K2;
    float* sW  = sm;                     // [KT][128]
    float* sAT = sm + (size_t)KT*HIDN;   // [<=128 k][RS]
    int tid = threadIdx.x;

    // stage W (float4, both sources)
    for (int idx = tid; idx < KT*32; idx += 256){
        int k = idx >> 5, qc = idx & 31;
        float4 v = (k < K1) ? *(const float4*)(W1 + (size_t)k*HIDN + qc*4)
                            : *(const float4*)(W2 + (size_t)(k-K1)*HIDN + qc*4);
        *(float4*)(sW + (size_t)k*HIDN + qc*4) = v;
    }
    int cg = tid >> 4;           // 0..15 col groups
    int rg = tid & 15;           // 0..15 row groups
    int c_lo = cg*4, c_hi = 64 + cg*4;
    float b[8];
    #pragma unroll
    for (int j = 0; j < 4; j++){ b[j] = bias[c_lo+j]; b[4+j] = bias[c_hi+j]; }

    int ntiles = (nrows + TILE_ROWS - 1) / TILE_ROWS;
    for (int tile = blockIdx.x; tile < ntiles; tile += gridDim.x){
        int rowbase = tile * TILE_ROWS;
        unsigned long long acc[8][4];
        #pragma unroll
        for (int i = 0; i < 8; i++)
            #pragma unroll
            for (int q = 0; q < 4; q++) acc[i][q] = 0ull;

        __syncthreads();   // protect prior-iter reads (and first-iter W staging)
        stage_A<K1, MODE>(sAT, A1, i0, i1, e0, e1, rowbase, nrows, tid);
        __syncthreads();
        mma_pass<K1>(sAT, sW, 0, rg, cg, acc);

        if (K2 > 0){
            __syncthreads();
            stage_A<K2, MPLAIN>(sAT, A2, nullptr, nullptr, nullptr, nullptr,
                                rowbase, nrows, tid);
            __syncthreads();
            mma_pass<K2>(sAT, sW, K1, rg, cg, acc);
        }

        // epilogue: bias (+relu), two float4 stores per row
        #pragma unroll
        for (int i = 0; i < 8; i++){
            int lrow = (i < 4) ? (rg*4 + i) : (64 + rg*4 + (i-4));
            int r = rowbase + lrow;
            if (r < nrows){
                float2 p0 = unpk2(acc[i][0]), p1 = unpk2(acc[i][1]);
                float2 p2 = unpk2(acc[i][2]), p3 = unpk2(acc[i][3]);
                float o0 = p0.x + b[0], o1 = p0.y + b[1], o2 = p1.x + b[2], o3 = p1.y + b[3];
                float o4 = p2.x + b[4], o5 = p2.y + b[5], o6 = p3.x + b[6], o7 = p3.y + b[7];
                if (relu){
                    o0 = fmaxf(o0,0.f); o1 = fmaxf(o1,0.f); o2 = fmaxf(o2,0.f); o3 = fmaxf(o3,0.f);
                    o4 = fmaxf(o4,0.f); o5 = fmaxf(o5,0.f); o6 = fmaxf(o6,0.f); o7 = fmaxf(o7,0.f);
                }
                *(float4*)(C + (size_t)r*HIDN + c_lo) = make_float4(o0,o1,o2,o3);
                *(float4*)(C + (size_t)r*HIDN + c_hi) = make_float4(o4,o5,o6,o7);
            }
        }
    }
}

// ---------------- launch ----------------
extern "C" void kernel_launch(void* const* d_in, const int* in_sizes, int n_in,
                              void* d_out, int out_size){
    const float* x_pol  = (const float*)d_in[0];
    const int*   psidx  = (const int*)  d_in[1];
    const float* x_comp = (const float*)d_in[2];
    const int*   csct   = (const int*)  d_in[3];
    const int*   cind   = (const int*)  d_in[4];
    const int*   eidx   = (const int*)  d_in[5];
    const float* semb   = (const float*)d_in[6];
    const float* scemb  = (const float*)d_in[7];
    const float* iemb   = (const float*)d_in[8];
    const float* W_pol  = (const float*)d_in[9];
    const float* b_pol  = (const float*)d_in[10];
    const float* W_comp = (const float*)d_in[11];
    const float* b_comp = (const float*)d_in[12];
    const float* Wl1    = (const float*)d_in[13];
    const float* bl1    = (const float*)d_in[14];
    const float* Wr1    = (const float*)d_in[15];
    const float* Wl2    = (const float*)d_in[16];
    const float* bl2    = (const float*)d_in[17];
    const float* Wr2    = (const float*)d_in[18];
    float* out = (float*)d_out;

    int NP = in_sizes[0]/64;
    int NC = in_sizes[2]/96;
    int E  = in_sizes[5]/2;
    int N  = NP + NC;
    const int* srcv = eidx;
    const int* dstv = eidx + E;

    float *hP, *h1P, *mP;
    cudaGetSymbolAddress((void**)&hP,  g_h);
    cudaGetSymbolAddress((void**)&h1P, g_h1);
    cudaGetSymbolAddress((void**)&mP,  g_m);

    const int SM_P = ( 72*HIDN + TILE_ROWS*RS)*4;
    const int SM_C = (112*HIDN + TILE_ROWS*RS)*4;
    const int SM_S = (256*HIDN + TILE_ROWS*RS)*4;
    cudaFuncSetAttribute(gemm_t< 72,  0, MPOL>,   cudaFuncAttributeMaxDynamicSharedMemorySize, SM_P);
    cudaFuncSetAttribute(gemm_t<112,  0, MCOMP>,  cudaFuncAttributeMaxDynamicSharedMemorySize, SM_C);
    cudaFuncSetAttribute(gemm_t<128,128, MPLAIN>, cudaFuncAttributeMaxDynamicSharedMemorySize, SM_S);

    // encoders (feature concat fused into A staging)
    gemm_t< 72,  0, MPOL><<<148, 256, SM_P>>>(
        x_pol, nullptr, psidx, nullptr, semb, nullptr,
        W_pol, nullptr, b_pol, hP, NP, 1);
    gemm_t<112,  0, MCOMP><<<148, 256, SM_C>>>(
        x_comp, nullptr, csct, cind, scemb, iemb,
        W_comp, nullptr, b_comp, hP + (size_t)NP*HIDN, NC, 1);

    // CSR build (shared by both layers)
    int NB = (N + 1023) / 1024;
    zero_deg   <<<NB, 1024>>>(N);
    count_deg  <<<2048, 256>>>(dstv, E);
    scan_blocks<<<NB, 1024>>>(N);
    scan_bsums <<<1, 256>>>(NB, N, E);
    add_bsums  <<<NB, 1024>>>(N);
    fill_csr   <<<2048, 256>>>(srcv, dstv, E);

    // SAGE layer 1
    agg_mean<<<(N + 7)/8, 256>>>(hP, mP, N);
    gemm_t<128,128, MPLAIN><<<148, 256, SM_S>>>(
        mP, hP, nullptr, nullptr, nullptr, nullptr,
        Wl1, Wr1, bl1, h1P, N, 1);

    // SAGE layer 2 -> d_out
    agg_mean<<<(N + 7)/8, 256>>>(h1P, mP, N);
    gemm_t<128,128, MPLAIN><<<148, 256, SM_S>>>(
        mP, h1P, nullptr, nullptr, nullptr, nullptr,
        Wl2, Wr2, bl2, out, N, 0);
}

// round 12
// speedup vs baseline: 2.7645x; 1.5702x over previous
#include <cuda_runtime.h>
#include <cuda_bf16.h>
#include <cstdint>

#define HIDN 128
#define MAXN 100001
#define MAXE 1600000

// ---------------- scratch (no allocations allowed) ----------------
__device__ float g_h [100000*HIDN];
__device__ float g_h1[100000*HIDN];
__device__ float g_m [100000*HIDN];
__device__ int   g_deg[MAXN];
__device__ int   g_off[MAXN];
__device__ int   g_cur[MAXN];
__device__ int   g_csrc[MAXE];
__device__ int   g_bsums[256];

// ---------------- split + pack helpers ----------------
// hi = truncate fp32 to bf16 (exact residual), lo = rn(x - hi)
__device__ __forceinline__ uint32_t pack_hi2(float x, float y){
    return (__float_as_uint(x) >> 16) | (__float_as_uint(y) & 0xFFFF0000u);
}
__device__ __forceinline__ uint32_t pack_lo2(float x, float y){
    float rx = x - __uint_as_float(__float_as_uint(x) & 0xFFFF0000u);
    float ry = y - __uint_as_float(__float_as_uint(y) & 0xFFFF0000u);
    uint32_t lx = (uint32_t)__bfloat16_as_ushort(__float2bfloat16(rx));
    uint32_t ly = (uint32_t)__bfloat16_as_ushort(__float2bfloat16(ry));
    return lx | (ly << 16);
}

// D += A(16x16 bf16) @ B(16x8 bf16), fp32 acc  — baseline PTX (sm_80+), HMMA on sm_103
__device__ __forceinline__ void mma16816(float* d, uint32_t a0, uint32_t a1, uint32_t a2, uint32_t a3,
                                         uint32_t b0, uint32_t b1){
    asm volatile(
        "mma.sync.aligned.m16n8k16.row.col.f32.bf16.bf16.f32 "
        "{%0,%1,%2,%3}, {%4,%5,%6,%7}, {%8,%9}, {%0,%1,%2,%3};"
        : "+f"(d[0]), "+f"(d[1]), "+f"(d[2]), "+f"(d[3])
        : "r"(a0), "r"(a1), "r"(a2), "r"(a3), "r"(b0), "r"(b1));
}

// ---------------- CSR build ----------------
__global__ void zero_deg(int n){
    int i = blockIdx.x*blockDim.x + threadIdx.x;
    if (i < n) g_deg[i] = 0;
}
__global__ void count_deg(const int* __restrict__ dstv, int E){
    for (int e = blockIdx.x*blockDim.x + threadIdx.x; e < E; e += gridDim.x*blockDim.x)
        atomicAdd(&g_deg[dstv[e]], 1);
}
__global__ void scan_blocks(int n){
    __shared__ int s[1024];
    int t = threadIdx.x;
    int g = blockIdx.x*1024 + t;
    int v = (g < n) ? g_deg[g] : 0;
    s[t] = v; __syncthreads();
    #pragma unroll
    for (int d = 1; d < 1024; d <<= 1){
        int x = (t >= d) ? s[t-d] : 0;
        __syncthreads();
        s[t] += x;
        __syncthreads();
    }
    if (g < n) g_off[g] = s[t] - v;
    if (t == 1023) g_bsums[blockIdx.x] = s[1023];
}
__global__ void scan_bsums(int nb, int n, int total){
    __shared__ int s[256];
    int t = threadIdx.x;
    int v = (t < nb) ? g_bsums[t] : 0;
    s[t] = v; __syncthreads();
    #pragma unroll
    for (int d = 1; d < 256; d <<= 1){
        int x = (t >= d) ? s[t-d] : 0;
        __syncthreads();
        s[t] += x;
        __syncthreads();
    }
    if (t < nb) g_bsums[t] = s[t] - v;
    if (t == 0) g_off[n] = total;
}
__global__ void add_bsums(int n){
    int g = blockIdx.x*1024 + threadIdx.x;
    if (g < n){
        int o = g_off[g] + g_bsums[blockIdx.x];
        g_off[g] = o;
        g_cur[g] = o;
    }
}
__global__ void fill_csr(const int* __restrict__ srcv, const int* __restrict__ dstv, int E){
    for (int e = blockIdx.x*blockDim.x + threadIdx.x; e < E; e += gridDim.x*blockDim.x){
        int d = dstv[e];
        int p = atomicAdd(&g_cur[d], 1);
        g_csrc[p] = srcv[e];
    }
}

// ---------------- mean aggregation: one warp per dst node ----------------
__global__ void agg_mean(const float* __restrict__ hin, float* __restrict__ mout, int n){
    int w    = (blockIdx.x*blockDim.x + threadIdx.x) >> 5;
    int lane = threadIdx.x & 31;
    if (w >= n) return;
    int beg = g_off[w], end = g_off[w+1];
    const float* base = hin + lane*4;
    float4 acc = make_float4(0.f, 0.f, 0.f, 0.f);
    int j = beg;
    for (; j + 16 <= end; j += 16){
        float4 v[16];
        #pragma unroll
        for (int t = 0; t < 16; t++){
            int s = g_csrc[j+t];
            v[t] = *(const float4*)(base + (size_t)s*HIDN);
        }
        #pragma unroll
        for (int t = 0; t < 16; t++){
            acc.x += v[t].x; acc.y += v[t].y; acc.z += v[t].z; acc.w += v[t].w;
        }
    }
    for (; j + 4 <= end; j += 4){
        float4 v[4];
        #pragma unroll
        for (int t = 0; t < 4; t++){
            int s = g_csrc[j+t];
            v[t] = *(const float4*)(base + (size_t)s*HIDN);
        }
        #pragma unroll
        for (int t = 0; t < 4; t++){
            acc.x += v[t].x; acc.y += v[t].y; acc.z += v[t].z; acc.w += v[t].w;
        }
    }
    for (; j < end; ++j){
        int s = g_csrc[j];
        float4 v = *(const float4*)(base + (size_t)s*HIDN);
        acc.x += v.x; acc.y += v.y; acc.z += v.z; acc.w += v.w;
    }
    int d = end - beg;
    float inv = 1.0f / (float)(d > 0 ? d : 1);
    float4 r = make_float4(acc.x*inv, acc.y*inv, acc.z*inv, acc.w*inv);
    *(float4*)(mout + (size_t)w*HIDN + lane*4) = r;
}

// ================= mma.sync GEMM =================
// C[nrows,128] = act( [A1 | A2] @ [W1 ; W2] + b ), fp32 I/O, bf16 3-split HMMA.
// Operands staged in smem in FRAGMENT-LINEAR order:
//   W slot ((chunk*16 + ntile)*32 + lane)*8B  = {b0,b1} of m16n8k16 B frag
//   A slot ((chunk*8  + mtile)*32 + lane)*16B = {a0,a1,a2,a3} of A frag
// hi split at base, lo split at base+SPLIT. Inner loop: conflict-free LDS.128/LDS.64 + HMMA.
// 8 warps: warp-row wr=w&3 (32 rows), warp-col wc=w>>2 (64 cols). acc 2x8x4 f32/thread.
enum { MPLAIN = 0, MPOL = 1, MCOMP = 2 };

template<int MODE, int LD, int KV>
__device__ __forceinline__ float elemA(const float* __restrict__ A,
        const float* __restrict__ e0, const float* __restrict__ e1,
        int i0v, int i1v, int r, int k)
{
    if (MODE == MPLAIN){
        if (KV % 16 != 0 && k >= KV) return 0.f;
        return A[(size_t)r*LD + k];
    } else if (MODE == MPOL){
        if (k < 64) return A[(size_t)r*64 + k];
        if (k < 72) return e0[(size_t)i0v*8 + (k-64)];
        return 0.f;
    } else {
        if (k < 96)  return A[(size_t)r*96 + k];
        if (k < 104) return e0[(size_t)i0v*8 + (k-96)];
        if (k < 112) return e1[(size_t)i1v*8 + (k-104)];
        return 0.f;
    }
}

// Stage one pass's A tile into fragment-linear smem (hi at sA, lo at sA+ASP).
template<int MODE, int LD, int KV, int NBC, int ASP>
__device__ __forceinline__ void stageA(
    uint8_t* __restrict__ sA, const float* __restrict__ A,
    const int* __restrict__ i0, const int* __restrict__ i1,
    const float* __restrict__ e0, const float* __restrict__ e1,
    int rowbase, int nrows, int tid)
{
    for (int idx = tid; idx < NBC*8*32; idx += 256){
        int l  = idx & 31;
        int t  = idx >> 5;
        int mt = t & 7;
        int c  = t >> 3;
        int gg = l >> 2, tt = l & 3;
        int r0 = rowbase + mt*16 + gg;
        int r1 = r0 + 8;
        int k0 = c*16 + tt*2;
        float x00=0.f,x01=0.f,x10=0.f,x11=0.f,x20=0.f,x21=0.f,x30=0.f,x31=0.f;
        int i00=0,i01=0,i10=0,i11=0;
        if (MODE == MPOL){
            if (r0 < nrows) i00 = i0[r0];
            if (r1 < nrows) i10 = i0[r1];
        } else if (MODE == MCOMP){
            if (r0 < nrows){ i00 = i0[r0]; i01 = i1[r0]; }
            if (r1 < nrows){ i10 = i0[r1]; i11 = i1[r1]; }
        }
        if (r0 < nrows){
            x00 = elemA<MODE,LD,KV>(A,e0,e1,i00,i01,r0,k0);
            x01 = elemA<MODE,LD,KV>(A,e0,e1,i00,i01,r0,k0+1);
            x20 = elemA<MODE,LD,KV>(A,e0,e1,i00,i01,r0,k0+8);
            x21 = elemA<MODE,LD,KV>(A,e0,e1,i00,i01,r0,k0+9);
        }
        if (r1 < nrows){
            x10 = elemA<MODE,LD,KV>(A,e0,e1,i10,i11,r1,k0);
            x11 = elemA<MODE,LD,KV>(A,e0,e1,i10,i11,r1,k0+1);
            x30 = elemA<MODE,LD,KV>(A,e0,e1,i10,i11,r1,k0+8);
            x31 = elemA<MODE,LD,KV>(A,e0,e1,i10,i11,r1,k0+9);
        }
        uint32_t slot = (uint32_t)idx * 16u;
        uint4 hi, lo;
        hi.x = pack_hi2(x00,x01); hi.y = pack_hi2(x10,x11);
        hi.z = pack_hi2(x20,x21); hi.w = pack_hi2(x30,x31);
        lo.x = pack_lo2(x00,x01); lo.y = pack_lo2(x10,x11);
        lo.z = pack_lo2(x20,x21); lo.w = pack_lo2(x30,x31);
        *(uint4*)(sA + slot)       = hi;
        *(uint4*)(sA + ASP + slot) = lo;
    }
}

template<int K1, int KC1, int K2, int KC2, int MODE>
__global__ void __launch_bounds__(256)
mgemm(const float* __restrict__ A1, const float* __restrict__ A2,
      const int* __restrict__ i0, const int* __restrict__ i1,
      const float* __restrict__ e0, const float* __restrict__ e1,
      const float* __restrict__ W1, const float* __restrict__ W2,
      const float* __restrict__ bias, float* __restrict__ C,
      int nrows, int relu)
{
    constexpr int KCT   = KC1 + KC2;
    constexpr int WSP   = KCT*16*32*8;                 // bytes per W split
    constexpr int KCMAX = (KC1 > KC2) ? KC1 : KC2;
    constexpr int ASP   = KCMAX*8*32*16;               // bytes per A split

    extern __shared__ uint8_t smem[];
    float*   sBias = (float*)smem;                     // 512 B
    uint8_t* sW    = smem + 512;                       // 2*WSP
    uint8_t* sA    = sW + 2*(size_t)WSP;               // 2*ASP

    int tid  = threadIdx.x;
    int w    = tid >> 5, lane = tid & 31;
    int wr   = w & 3,    wc   = w >> 2;
    int g    = lane >> 2, tg  = lane & 3;

    // ---- stage W (both splits, fragment-linear), zero-padded ----
    for (int idx = tid; idx < KCT*16*32; idx += 256){
        int l  = idx & 31;
        int t  = idx >> 5;
        int nt = t & 15;
        int c  = t >> 4;
        int gg = l >> 2, tt = l & 3;
        int n  = nt*8 + gg;
        int kg = c*16 + tt*2;
        float wv[4];
        #pragma unroll
        for (int q = 0; q < 4; q++){
            int k = kg + ((q & 1) ? 1 : 0) + ((q >> 1) ? 8 : 0);  // k, k+1, k+8, k+9
            float v = 0.f;
            if (k < KC1*16){
                if (k < K1) v = W1[(size_t)k*128 + n];
            } else {
                int k2 = k - KC1*16;
                if (k2 < K2) v = W2[(size_t)k2*128 + n];
            }
            wv[q] = v;
        }
        uint32_t slot = (uint32_t)idx * 8u;
        *(uint2*)(sW + slot)       = make_uint2(pack_hi2(wv[0],wv[1]), pack_hi2(wv[2],wv[3]));
        *(uint2*)(sW + WSP + slot) = make_uint2(pack_lo2(wv[0],wv[1]), pack_lo2(wv[2],wv[3]));
    }
    for (int i = tid; i < 128; i += 256) sBias[i] = bias[i];
    __syncthreads();

    int ntiles = (nrows + 127) >> 7;
    for (int tile = blockIdx.x; tile < ntiles; tile += gridDim.x){
        int rowbase = tile << 7;
        float acc[2][8][4];
        #pragma unroll
        for (int i = 0; i < 2; i++)
            #pragma unroll
            for (int j = 0; j < 8; j++)
                #pragma unroll
                for (int q = 0; q < 4; q++) acc[i][j][q] = 0.f;

        // ---- pass 0 ----
        __syncthreads();   // prior tile's mma reads done before overwrite
        stageA<MODE, K1, K1, KC1, ASP>(sA, A1, i0, i1, e0, e1, rowbase, nrows, tid);
        __syncthreads();
        #pragma unroll 2
        for (int c = 0; c < KC1; c++){
            const uint8_t* ab = sA + (((uint32_t)c*8 + wr*2)*32 + lane)*16u;
            uint4 ah0 = *(const uint4*)(ab);
            uint4 ah1 = *(const uint4*)(ab + 512);
            uint4 al0 = *(const uint4*)(ab + ASP);
            uint4 al1 = *(const uint4*)(ab + ASP + 512);
            const uint8_t* bb = sW + (((uint32_t)c*16 + wc*8)*32 + lane)*8u;
            #pragma unroll
            for (int nt = 0; nt < 8; nt++){
                uint2 bh = *(const uint2*)(bb + nt*256);
                uint2 bl = *(const uint2*)(bb + WSP + nt*256);
                mma16816(acc[0][nt], ah0.x, ah0.y, ah0.z, ah0.w, bh.x, bh.y);
                mma16816(acc[1][nt], ah1.x, ah1.y, ah1.z, ah1.w, bh.x, bh.y);
                mma16816(acc[0][nt], ah0.x, ah0.y, ah0.z, ah0.w, bl.x, bl.y);
                mma16816(acc[1][nt], ah1.x, ah1.y, ah1.z, ah1.w, bl.x, bl.y);
                mma16816(acc[0][nt], al0.x, al0.y, al0.z, al0.w, bh.x, bh.y);
                mma16816(acc[1][nt], al1.x, al1.y, al1.z, al1.w, bh.x, bh.y);
            }
        }

        // ---- pass 1 (A2, W chunks KC1..) ----
        if (KC2 > 0){
            __syncthreads();
            stageA<MPLAIN, K2, K2, KC2, ASP>(sA, A2, nullptr, nullptr, nullptr, nullptr,
                                             rowbase, nrows, tid);
            __syncthreads();
            #pragma unroll 2
            for (int c = 0; c < KC2; c++){
                const uint8_t* ab = sA + (((uint32_t)c*8 + wr*2)*32 + lane)*16u;
                uint4 ah0 = *(const uint4*)(ab);
                uint4 ah1 = *(const uint4*)(ab + 512);
                uint4 al0 = *(const uint4*)(ab + ASP);
                uint4 al1 = *(const uint4*)(ab + ASP + 512);
                const uint8_t* bb = sW + (((uint32_t)(KC1 + c)*16 + wc*8)*32 + lane)*8u;
                #pragma unroll
                for (int nt = 0; nt < 8; nt++){
                    uint2 bh = *(const uint2*)(bb + nt*256);
                    uint2 bl = *(const uint2*)(bb + WSP + nt*256);
                    mma16816(acc[0][nt], ah0.x, ah0.y, ah0.z, ah0.w, bh.x, bh.y);
                    mma16816(acc[1][nt], ah1.x, ah1.y, ah1.z, ah1.w, bh.x, bh.y);
                    mma16816(acc[0][nt], ah0.x, ah0.y, ah0.z, ah0.w, bl.x, bl.y);
                    mma16816(acc[1][nt], ah1.x, ah1.y, ah1.z, ah1.w, bl.x, bl.y);
                    mma16816(acc[0][nt], al0.x, al0.y, al0.z, al0.w, bh.x, bh.y);
                    mma16816(acc[1][nt], al1.x, al1.y, al1.z, al1.w, bh.x, bh.y);
                }
            }
        }

        // ---- epilogue: bias (+relu), float2 stores ----
        #pragma unroll
        for (int mt = 0; mt < 2; mt++){
            int r0 = rowbase + wr*32 + mt*16 + g;
            int r1 = r0 + 8;
            #pragma unroll
            for (int nt = 0; nt < 8; nt++){
                int col = wc*64 + nt*8 + tg*2;
                float b0 = sBias[col], b1 = sBias[col+1];
                float c0 = acc[mt][nt][0] + b0, c1 = acc[mt][nt][1] + b1;
                float c2 = acc[mt][nt][2] + b0, c3 = acc[mt][nt][3] + b1;
                if (relu){
                    c0 = fmaxf(c0,0.f); c1 = fmaxf(c1,0.f);
                    c2 = fmaxf(c2,0.f); c3 = fmaxf(c3,0.f);
                }
                if (r0 < nrows) *(float2*)(C + (size_t)r0*HIDN + col) = make_float2(c0,c1);
                if (r1 < nrows) *(float2*)(C + (size_t)r1*HIDN + col) = make_float2(c2,c3);
            }
        }
    }
}

// ---------------- launch ----------------
extern "C" void kernel_launch(void* const* d_in, const int* in_sizes, int n_in,
                              void* d_out, int out_size){
    const float* x_pol  = (const float*)d_in[0];
    const int*   psidx  = (const int*)  d_in[1];
    const float* x_comp = (const float*)d_in[2];
    const int*   csct   = (const int*)  d_in[3];
    const int*   cind   = (const int*)  d_in[4];
    const int*   eidx   = (const int*)  d_in[5];
    const float* semb   = (const float*)d_in[6];
    const float* scemb  = (const float*)d_in[7];
    const float* iemb   = (const float*)d_in[8];
    const float* W_pol  = (const float*)d_in[9];
    const float* b_pol  = (const float*)d_in[10];
    const float* W_comp = (const float*)d_in[11];
    const float* b_comp = (const float*)d_in[12];
    const float* Wl1    = (const float*)d_in[13];
    const float* bl1    = (const float*)d_in[14];
    const float* Wr1    = (const float*)d_in[15];
    const float* Wl2    = (const float*)d_in[16];
    const float* bl2    = (const float*)d_in[17];
    const float* Wr2    = (const float*)d_in[18];
    float* out = (float*)d_out;

    int NP = in_sizes[0]/64;
    int NC = in_sizes[2]/96;
    int E  = in_sizes[5]/2;
    int N  = NP + NC;
    const int* srcv = eidx;
    const int* dstv = eidx + E;

    float *hP, *h1P, *mP;
    cudaGetSymbolAddress((void**)&hP,  g_h);
    cudaGetSymbolAddress((void**)&h1P, g_h1);
    cudaGetSymbolAddress((void**)&mP,  g_m);

    // smem = 512 bias + 2*WSP + 2*ASP
    const int SM_POL  = 512 + 2*( 5*16*32*8) + 2*(5*8*32*16);   //  82,432
    const int SM_COMP = 512 + 2*( 7*16*32*8) + 2*(7*8*32*16);   // 115,200
    const int SM_SAGE = 512 + 2*(16*16*32*8) + 2*(8*8*32*16);   // 197,120
    cudaFuncSetAttribute(mgemm< 72, 5,   0, 0, MPOL>,   cudaFuncAttributeMaxDynamicSharedMemorySize, SM_POL);
    cudaFuncSetAttribute(mgemm<112, 7,   0, 0, MCOMP>,  cudaFuncAttributeMaxDynamicSharedMemorySize, SM_COMP);
    cudaFuncSetAttribute(mgemm<128, 8, 128, 8, MPLAIN>, cudaFuncAttributeMaxDynamicSharedMemorySize, SM_SAGE);

    // encoders (feature concat fused into fragment staging)
    mgemm< 72, 5,   0, 0, MPOL><<<148, 256, SM_POL>>>(
        x_pol, nullptr, psidx, nullptr, semb, nullptr,
        W_pol, nullptr, b_pol, hP, NP, 1);
    mgemm<112, 7,   0, 0, MCOMP><<<148, 256, SM_COMP>>>(
        x_comp, nullptr, csct, cind, scemb, iemb,
        W_comp, nullptr, b_comp, hP + (size_t)NP*HIDN, NC, 1);

    // CSR build (shared by both layers)
    int NB = (N + 1023) / 1024;
    zero_deg   <<<NB, 1024>>>(N);
    count_deg  <<<2048, 256>>>(dstv, E);
    scan_blocks<<<NB, 1024>>>(N);
    scan_bsums <<<1, 256>>>(NB, N, E);
    add_bsums  <<<NB, 1024>>>(N);
    fill_csr   <<<2048, 256>>>(srcv, dstv, E);

    // SAGE layer 1
    agg_mean<<<(N + 7)/8, 256>>>(hP, mP, N);
    mgemm<128, 8, 128, 8, MPLAIN><<<148, 256, SM_SAGE>>>(
        mP, hP, nullptr, nullptr, nullptr, nullptr,
        Wl1, Wr1, bl1, h1P, N, 1);

    // SAGE layer 2 -> d_out
    agg_mean<<<(N + 7)/8, 256>>>(h1P, mP, N);
    mgemm<128, 8, 128, 8, MPLAIN><<<148, 256, SM_SAGE>>>(
        mP, h1P, nullptr, nullptr, nullptr, nullptr,
        Wl2, Wr2, bl2, out, N, 0);
}

// round 13
// speedup vs baseline: 2.9185x; 1.0557x over previous
#include <cuda_runtime.h>
#include <cuda_bf16.h>
#include <cstdint>

#define HIDN 128
#define MAXN 100001
#define MAXE 1600000

// ---------------- scratch (no allocations allowed) ----------------
__device__ float g_h [100000*HIDN];
__device__ float g_h1[100000*HIDN];
__device__ float g_m [100000*HIDN];
__device__ int   g_deg[MAXN];
__device__ int   g_off[MAXN];
__device__ int   g_cur[MAXN];
__device__ int   g_csrc[MAXE];
__device__ int   g_bsums[256];

// ---------------- split + pack helpers ----------------
__device__ __forceinline__ uint32_t pack_hi2(float x, float y){
    return (__float_as_uint(x) >> 16) | (__float_as_uint(y) & 0xFFFF0000u);
}
__device__ __forceinline__ uint32_t pack_lo2(float x, float y){
    float rx = x - __uint_as_float(__float_as_uint(x) & 0xFFFF0000u);
    float ry = y - __uint_as_float(__float_as_uint(y) & 0xFFFF0000u);
    uint32_t lx = (uint32_t)__bfloat16_as_ushort(__float2bfloat16(rx));
    uint32_t ly = (uint32_t)__bfloat16_as_ushort(__float2bfloat16(ry));
    return lx | (ly << 16);
}

// D += A(16x16 bf16) @ B(16x8 bf16), fp32 acc — baseline PTX, HMMA on sm_103
__device__ __forceinline__ void mma16816(float* d, uint32_t a0, uint32_t a1, uint32_t a2, uint32_t a3,
                                         uint32_t b0, uint32_t b1){
    asm volatile(
        "mma.sync.aligned.m16n8k16.row.col.f32.bf16.bf16.f32 "
        "{%0,%1,%2,%3}, {%4,%5,%6,%7}, {%8,%9}, {%0,%1,%2,%3};"
        : "+f"(d[0]), "+f"(d[1]), "+f"(d[2]), "+f"(d[3])
        : "r"(a0), "r"(a1), "r"(a2), "r"(a3), "r"(b0), "r"(b1));
}

// ---------------- CSR build ----------------
__global__ void zero_deg(int n){
    int i = blockIdx.x*blockDim.x + threadIdx.x;
    if (i < n) g_deg[i] = 0;
}
__global__ void count_deg(const int* __restrict__ dstv, int E){
    for (int e = blockIdx.x*blockDim.x + threadIdx.x; e < E; e += gridDim.x*blockDim.x)
        atomicAdd(&g_deg[dstv[e]], 1);
}
__global__ void scan_blocks(int n){
    __shared__ int s[1024];
    int t = threadIdx.x;
    int g = blockIdx.x*1024 + t;
    int v = (g < n) ? g_deg[g] : 0;
    s[t] = v; __syncthreads();
    #pragma unroll
    for (int d = 1; d < 1024; d <<= 1){
        int x = (t >= d) ? s[t-d] : 0;
        __syncthreads();
        s[t] += x;
        __syncthreads();
    }
    if (g < n) g_off[g] = s[t] - v;
    if (t == 1023) g_bsums[blockIdx.x] = s[1023];
}
__global__ void scan_bsums(int nb, int n, int total){
    __shared__ int s[256];
    int t = threadIdx.x;
    int v = (t < nb) ? g_bsums[t] : 0;
    s[t] = v; __syncthreads();
    #pragma unroll
    for (int d = 1; d < 256; d <<= 1){
        int x = (t >= d) ? s[t-d] : 0;
        __syncthreads();
        s[t] += x;
        __syncthreads();
    }
    if (t < nb) g_bsums[t] = s[t] - v;
    if (t == 0) g_off[n] = total;
}
__global__ void add_bsums(int n){
    int g = blockIdx.x*1024 + threadIdx.x;
    if (g < n){
        int o = g_off[g] + g_bsums[blockIdx.x];
        g_off[g] = o;
        g_cur[g] = o;
    }
}
__global__ void fill_csr(const int* __restrict__ srcv, const int* __restrict__ dstv, int E){
    for (int e = blockIdx.x*blockDim.x + threadIdx.x; e < E; e += gridDim.x*blockDim.x){
        int d = dstv[e];
        int p = atomicAdd(&g_cur[d], 1);
        g_csrc[p] = srcv[e];
    }
}

// ---------------- mean aggregation: one warp per dst node ----------------
__global__ void agg_mean(const float* __restrict__ hin, float* __restrict__ mout, int n){
    int w    = (blockIdx.x*blockDim.x + threadIdx.x) >> 5;
    int lane = threadIdx.x & 31;
    if (w >= n) return;
    int beg = g_off[w], end = g_off[w+1];
    const float* base = hin + lane*4;
    float4 acc = make_float4(0.f, 0.f, 0.f, 0.f);
    int j = beg;
    for (; j + 16 <= end; j += 16){
        float4 v[16];
        #pragma unroll
        for (int t = 0; t < 16; t++){
            int s = g_csrc[j+t];
            v[t] = *(const float4*)(base + (size_t)s*HIDN);
        }
        #pragma unroll
        for (int t = 0; t < 16; t++){
            acc.x += v[t].x; acc.y += v[t].y; acc.z += v[t].z; acc.w += v[t].w;
        }
    }
    for (; j + 4 <= end; j += 4){
        float4 v[4];
        #pragma unroll
        for (int t = 0; t < 4; t++){
            int s = g_csrc[j+t];
            v[t] = *(const float4*)(base + (size_t)s*HIDN);
        }
        #pragma unroll
        for (int t = 0; t < 4; t++){
            acc.x += v[t].x; acc.y += v[t].y; acc.z += v[t].z; acc.w += v[t].w;
        }
    }
    for (; j < end; ++j){
        int s = g_csrc[j];
        float4 v = *(const float4*)(base + (size_t)s*HIDN);
        acc.x += v.x; acc.y += v.y; acc.z += v.z; acc.w += v.w;
    }
    int d = end - beg;
    float inv = 1.0f / (float)(d > 0 ? d : 1);
    float4 r = make_float4(acc.x*inv, acc.y*inv, acc.z*inv, acc.w*inv);
    *(float4*)(mout + (size_t)w*HIDN + lane*4) = r;
}

// ================= mma.sync GEMM (A direct-to-registers, no A smem) =================
// C[nrows,128] = act( [A1 | A2] @ [W1 ; W2] + b ). 8 warps = 4 row x 2 col.
// A rows are partitioned across warps -> each warp LDGs its own A fragments
// straight from global, converts (hi/lo bf16 split) in registers. W fragments
// (both splits) staged once in smem in fragment-linear order. Tile loop has NO
// __syncthreads. Inner loop software-pipelined: chunk c+1 LDG during chunk c HMMAs.
enum { MPLAIN = 0, MPOL = 1, MCOMP = 2 };

template<int MODE>
__device__ __forceinline__ float elemA(const float* __restrict__ A,
        const float* __restrict__ e0, const float* __restrict__ e1,
        int i0v, int i1v, int r, int k)
{
    if (MODE == MPOL){
        if (k < 64) return A[(size_t)r*64 + k];
        if (k < 72) return e0[(size_t)i0v*8 + (k-64)];
        return 0.f;
    } else { // MCOMP
        if (k < 96)  return A[(size_t)r*96 + k];
        if (k < 104) return e0[(size_t)i0v*8 + (k-96)];
        if (k < 112) return e1[(size_t)i1v*8 + (k-104)];
        return 0.f;
    }
}

template<int MODE, int LD>
__device__ __forceinline__ void loadfrag(
    const float* __restrict__ A, const float* __restrict__ e0, const float* __restrict__ e1,
    int i00, int i01, int i10, int i11,
    int r0, int r1, int nrows, int k0,
    uint4& ah, uint4& al)
{
    float x00=0.f,x01=0.f,x10=0.f,x11=0.f,x20=0.f,x21=0.f,x30=0.f,x31=0.f;
    if (MODE == MPLAIN){
        if (r0 < nrows){
            float2 p = *(const float2*)(A + (size_t)r0*LD + k0);
            float2 q = *(const float2*)(A + (size_t)r0*LD + k0 + 8);
            x00=p.x; x01=p.y; x20=q.x; x21=q.y;
        }
        if (r1 < nrows){
            float2 p = *(const float2*)(A + (size_t)r1*LD + k0);
            float2 q = *(const float2*)(A + (size_t)r1*LD + k0 + 8);
            x10=p.x; x11=p.y; x30=q.x; x31=q.y;
        }
    } else {
        if (r0 < nrows){
            x00 = elemA<MODE>(A,e0,e1,i00,i01,r0,k0);
            x01 = elemA<MODE>(A,e0,e1,i00,i01,r0,k0+1);
            x20 = elemA<MODE>(A,e0,e1,i00,i01,r0,k0+8);
            x21 = elemA<MODE>(A,e0,e1,i00,i01,r0,k0+9);
        }
        if (r1 < nrows){
            x10 = elemA<MODE>(A,e0,e1,i10,i11,r1,k0);
            x11 = elemA<MODE>(A,e0,e1,i10,i11,r1,k0+1);
            x30 = elemA<MODE>(A,e0,e1,i10,i11,r1,k0+8);
            x31 = elemA<MODE>(A,e0,e1,i10,i11,r1,k0+9);
        }
    }
    ah.x = pack_hi2(x00,x01); ah.y = pack_hi2(x10,x11);
    ah.z = pack_hi2(x20,x21); ah.w = pack_hi2(x30,x31);
    al.x = pack_lo2(x00,x01); al.y = pack_lo2(x10,x11);
    al.z = pack_lo2(x20,x21); al.w = pack_lo2(x30,x31);
}

template<int MODE, int LD, int KC, int WSPB>
__device__ __forceinline__ void gpass(
    const float* __restrict__ A, const float* __restrict__ e0, const float* __restrict__ e1,
    const int* __restrict__ i0, const int* __restrict__ i1,
    const uint8_t* __restrict__ sW, int wchunk0,
    int rowbase, int nrows, int wr, int wc, int lane,
    float acc[2][8][4])
{
    int g = lane >> 2, tt = lane & 3;
    int k0l = tt*2;
    int r0[2], r1[2];
    int ia[2][2], ib[2][2];
    #pragma unroll
    for (int mt = 0; mt < 2; mt++){
        r0[mt] = rowbase + wr*32 + mt*16 + g;
        r1[mt] = r0[mt] + 8;
        ia[mt][0]=ia[mt][1]=ib[mt][0]=ib[mt][1]=0;
        if (MODE != MPLAIN){
            if (r0[mt] < nrows){ ia[mt][0] = i0[r0[mt]]; if (MODE==MCOMP) ib[mt][0] = i1[r0[mt]]; }
            if (r1[mt] < nrows){ ia[mt][1] = i0[r1[mt]]; if (MODE==MCOMP) ib[mt][1] = i1[r1[mt]]; }
        }
    }

    uint4 cah[2], cal[2];
    #pragma unroll
    for (int mt = 0; mt < 2; mt++)
        loadfrag<MODE,LD>(A,e0,e1, ia[mt][0],ib[mt][0],ia[mt][1],ib[mt][1],
                          r0[mt],r1[mt],nrows, k0l, cah[mt], cal[mt]);

    #pragma unroll 2
    for (int c = 0; c < KC; c++){
        uint4 nah[2], nal[2];
        if (c + 1 < KC){
            #pragma unroll
            for (int mt = 0; mt < 2; mt++)
                loadfrag<MODE,LD>(A,e0,e1, ia[mt][0],ib[mt][0],ia[mt][1],ib[mt][1],
                                  r0[mt],r1[mt],nrows, (c+1)*16 + k0l, nah[mt], nal[mt]);
        }
        const uint8_t* bb = sW + (((uint32_t)(wchunk0 + c)*16 + wc*8)*32 + lane)*8u;
        #pragma unroll
        for (int nt = 0; nt < 8; nt++){
            uint2 bh = *(const uint2*)(bb + nt*256);
            uint2 bl = *(const uint2*)(bb + WSPB + nt*256);
            mma16816(acc[0][nt], cah[0].x, cah[0].y, cah[0].z, cah[0].w, bh.x, bh.y);
            mma16816(acc[1][nt], cah[1].x, cah[1].y, cah[1].z, cah[1].w, bh.x, bh.y);
            mma16816(acc[0][nt], cah[0].x, cah[0].y, cah[0].z, cah[0].w, bl.x, bl.y);
            mma16816(acc[1][nt], cah[1].x, cah[1].y, cah[1].z, cah[1].w, bl.x, bl.y);
            mma16816(acc[0][nt], cal[0].x, cal[0].y, cal[0].z, cal[0].w, bh.x, bh.y);
            mma16816(acc[1][nt], cal[1].x, cal[1].y, cal[1].z, cal[1].w, bh.x, bh.y);
        }
        cah[0]=nah[0]; cah[1]=nah[1]; cal[0]=nal[0]; cal[1]=nal[1];
    }
}

template<int K1, int KC1, int K2, int KC2, int MODE>
__global__ void __launch_bounds__(256)
mgemm(const float* __restrict__ A1, const float* __restrict__ A2,
      const int* __restrict__ i0, const int* __restrict__ i1,
      const float* __restrict__ e0, const float* __restrict__ e1,
      const float* __restrict__ W1, const float* __restrict__ W2,
      const float* __restrict__ bias, float* __restrict__ C,
      int nrows, int relu)
{
    constexpr int KCT = KC1 + KC2;
    constexpr int WSP = KCT*16*32*8;     // bytes per W split (fragment-linear)

    extern __shared__ uint8_t smem[];
    float*   sBias = (float*)smem;       // 512 B
    uint8_t* sW    = smem + 512;         // 2*WSP

    int tid  = threadIdx.x;
    int w    = tid >> 5, lane = tid & 31;
    int wr   = w & 3,    wc   = w >> 2;
    int g    = lane >> 2, tg  = lane & 3;

    // ---- stage W (both splits, fragment-linear), zero-padded ----
    for (int idx = tid; idx < KCT*16*32; idx += 256){
        int l  = idx & 31;
        int t  = idx >> 5;
        int nt = t & 15;
        int c  = t >> 4;
        int gg = l >> 2, tt = l & 3;
        int n  = nt*8 + gg;
        int kg = c*16 + tt*2;
        float wv[4];
        #pragma unroll
        for (int q = 0; q < 4; q++){
            int k = kg + ((q & 1) ? 1 : 0) + ((q >> 1) ? 8 : 0);
            float v = 0.f;
            if (k < KC1*16){
                if (k < K1) v = W1[(size_t)k*128 + n];
            } else {
                int k2 = k - KC1*16;
                if (k2 < K2) v = W2[(size_t)k2*128 + n];
            }
            wv[q] = v;
        }
        uint32_t slot = (uint32_t)idx * 8u;
        *(uint2*)(sW + slot)       = make_uint2(pack_hi2(wv[0],wv[1]), pack_hi2(wv[2],wv[3]));
        *(uint2*)(sW + WSP + slot) = make_uint2(pack_lo2(wv[0],wv[1]), pack_lo2(wv[2],wv[3]));
    }
    for (int i = tid; i < 128; i += 256) sBias[i] = bias[i];
    __syncthreads();

    int ntiles = (nrows + 127) >> 7;
    for (int tile = blockIdx.x; tile < ntiles; tile += gridDim.x){
        int rowbase = tile << 7;
        float acc[2][8][4];
        #pragma unroll
        for (int i = 0; i < 2; i++)
            #pragma unroll
            for (int j = 0; j < 8; j++)
                #pragma unroll
                for (int q = 0; q < 4; q++) acc[i][j][q] = 0.f;

        gpass<MODE, K1, KC1, WSP>(A1, e0, e1, i0, i1, sW, 0,
                                  rowbase, nrows, wr, wc, lane, acc);
        if (KC2 > 0)
            gpass<MPLAIN, K2, KC2, WSP>(A2, nullptr, nullptr, nullptr, nullptr, sW, KC1,
                                        rowbase, nrows, wr, wc, lane, acc);

        // ---- epilogue: bias (+relu), float2 stores ----
        #pragma unroll
        for (int mt = 0; mt < 2; mt++){
            int r0 = rowbase + wr*32 + mt*16 + g;
            int r1 = r0 + 8;
            #pragma unroll
            for (int nt = 0; nt < 8; nt++){
                int col = wc*64 + nt*8 + tg*2;
                float b0 = sBias[col], b1 = sBias[col+1];
                float c0 = acc[mt][nt][0] + b0, c1 = acc[mt][nt][1] + b1;
                float c2 = acc[mt][nt][2] + b0, c3 = acc[mt][nt][3] + b1;
                if (relu){
                    c0 = fmaxf(c0,0.f); c1 = fmaxf(c1,0.f);
                    c2 = fmaxf(c2,0.f); c3 = fmaxf(c3,0.f);
                }
                if (r0 < nrows) *(float2*)(C + (size_t)r0*HIDN + col) = make_float2(c0,c1);
                if (r1 < nrows) *(float2*)(C + (size_t)r1*HIDN + col) = make_float2(c2,c3);
            }
        }
    }
}

// ---------------- launch ----------------
extern "C" void kernel_launch(void* const* d_in, const int* in_sizes, int n_in,
                              void* d_out, int out_size){
    const float* x_pol  = (const float*)d_in[0];
    const int*   psidx  = (const int*)  d_in[1];
    const float* x_comp = (const float*)d_in[2];
    const int*   csct   = (const int*)  d_in[3];
    const int*   cind   = (const int*)  d_in[4];
    const int*   eidx   = (const int*)  d_in[5];
    const float* semb   = (const float*)d_in[6];
    const float* scemb  = (const float*)d_in[7];
    const float* iemb   = (const float*)d_in[8];
    const float* W_pol  = (const float*)d_in[9];
    const float* b_pol  = (const float*)d_in[10];
    const float* W_comp = (const float*)d_in[11];
    const float* b_comp = (const float*)d_in[12];
    const float* Wl1    = (const float*)d_in[13];
    const float* bl1    = (const float*)d_in[14];
    const float* Wr1    = (const float*)d_in[15];
    const float* Wl2    = (const float*)d_in[16];
    const float* bl2    = (const float*)d_in[17];
    const float* Wr2    = (const float*)d_in[18];
    float* out = (float*)d_out;

    int NP = in_sizes[0]/64;
    int NC = in_sizes[2]/96;
    int E  = in_sizes[5]/2;
    int N  = NP + NC;
    const int* srcv = eidx;
    const int* dstv = eidx + E;

    float *hP, *h1P, *mP;
    cudaGetSymbolAddress((void**)&hP,  g_h);
    cudaGetSymbolAddress((void**)&h1P, g_h1);
    cudaGetSymbolAddress((void**)&mP,  g_m);

    const int SM_POL  = 512 + 2*( 5*16*32*8);   //  41,472
    const int SM_COMP = 512 + 2*( 7*16*32*8);   //  57,856
    const int SM_SAGE = 512 + 2*(16*16*32*8);   // 131,584
    cudaFuncSetAttribute(mgemm< 72, 5,   0, 0, MPOL>,   cudaFuncAttributeMaxDynamicSharedMemorySize, SM_POL);
    cudaFuncSetAttribute(mgemm<112, 7,   0, 0, MCOMP>,  cudaFuncAttributeMaxDynamicSharedMemorySize, SM_COMP);
    cudaFuncSetAttribute(mgemm<128, 8, 128, 8, MPLAIN>, cudaFuncAttributeMaxDynamicSharedMemorySize, SM_SAGE);

    // fork-join: CSR build on a side stream, concurrent with encoders
    static cudaStream_t s_csr = nullptr;
    static cudaEvent_t  ev_fork = nullptr, ev_join = nullptr;
    if (!s_csr){
        cudaStreamCreateWithFlags(&s_csr, cudaStreamNonBlocking);
        cudaEventCreateWithFlags(&ev_fork, cudaEventDisableTiming);
        cudaEventCreateWithFlags(&ev_join, cudaEventDisableTiming);
    }

    cudaEventRecord(ev_fork, 0);
    cudaStreamWaitEvent(s_csr, ev_fork, 0);

    // CSR build on side stream
    int NB = (N + 1023) / 1024;
    zero_deg   <<<NB, 1024, 0, s_csr>>>(N);
    count_deg  <<<2048, 256, 0, s_csr>>>(dstv, E);
    scan_blocks<<<NB, 1024, 0, s_csr>>>(N);
    scan_bsums <<<1, 256,   0, s_csr>>>(NB, N, E);
    add_bsums  <<<NB, 1024, 0, s_csr>>>(N);
    fill_csr   <<<2048, 256, 0, s_csr>>>(srcv, dstv, E);
    cudaEventRecord(ev_join, s_csr);

    // encoders on main stream (concurrent with CSR build)
    mgemm< 72, 5,   0, 0, MPOL><<<148, 256, SM_POL>>>(
        x_pol, nullptr, psidx, nullptr, semb, nullptr,
        W_pol, nullptr, b_pol, hP, NP, 1);
    mgemm<112, 7,   0, 0, MCOMP><<<148, 256, SM_COMP>>>(
        x_comp, nullptr, csct, cind, scemb, iemb,
        W_comp, nullptr, b_comp, hP + (size_t)NP*HIDN, NC, 1);

    cudaStreamWaitEvent(0, ev_join, 0);   // join: agg needs CSR + h

    // SAGE layer 1
    agg_mean<<<(N + 7)/8, 256>>>(hP, mP, N);
    mgemm<128, 8, 128, 8, MPLAIN><<<148, 256, SM_SAGE>>>(
        mP, hP, nullptr, nullptr, nullptr, nullptr,
        Wl1, Wr1, bl1, h1P, N, 1);

    // SAGE layer 2 -> d_out
    agg_mean<<<(N + 7)/8, 256>>>(h1P, mP, N);
    mgemm<128, 8, 128, 8, MPLAIN><<<148, 256, SM_SAGE>>>(
        mP, h1P, nullptr, nullptr, nullptr, nullptr,
        Wl2, Wr2, bl2, out, N, 0);
}